// round 1
// baseline (speedup 1.0000x reference)
#include <cuda_runtime.h>

#define C 512
#define FULLMASK 0xffffffffu

// ---- scratch (no allocs allowed) -------------------------------------------
__device__ float g_xavr[C];
__device__ float g_bv[C];
__device__ float g_xtmp[C];
__device__ float g_xsparse[C];
__device__ float g_scale[C];
__device__ float g_coeff;   // 0.05 / norm (or 0.05 if norm invalid)

// ---- K1: per-channel mean ---------------------------------------------------
// one block per channel; 1024 threads; float4 streaming loads
__global__ void k_channel_mean(const float* __restrict__ x, int hw) {
    const int c = blockIdx.x;
    const float4* xp = reinterpret_cast<const float4*>(x + (size_t)c * hw);
    const int n4 = hw >> 2;
    float s = 0.f;
    for (int i = threadIdx.x; i < n4; i += blockDim.x) {
        float4 v = __ldg(xp + i);
        s += (v.x + v.y) + (v.z + v.w);
    }
    __shared__ float sm[32];
    #pragma unroll
    for (int o = 16; o; o >>= 1) s += __shfl_xor_sync(FULLMASK, s, o);
    const int lane = threadIdx.x & 31, w = threadIdx.x >> 5;
    if (lane == 0) sm[w] = s;
    __syncthreads();
    if (w == 0) {
        s = (lane < (int)(blockDim.x >> 5)) ? sm[lane] : 0.f;
        #pragma unroll
        for (int o = 16; o; o >>= 1) s += __shfl_xor_sync(FULLMASK, s, o);
        if (lane == 0) g_xavr[c] = s / (float)hw;
    }
}

// ---- K2a: boost_vec = W @ x_avr (one row per block, 128 threads) ------------
__global__ void k_matvec(const float* __restrict__ W) {
    __shared__ float av[C];
    const int t = threadIdx.x;  // 128 threads
    #pragma unroll
    for (int j = t; j < C; j += 128) av[j] = g_xavr[j];
    __syncthreads();
    const int row = blockIdx.x;
    float4 wv = __ldg(reinterpret_cast<const float4*>(W + (size_t)row * C) + t);
    float s = wv.x * av[4*t] + wv.y * av[4*t+1] + wv.z * av[4*t+2] + wv.w * av[4*t+3];
    #pragma unroll
    for (int o = 16; o; o >>= 1) s += __shfl_xor_sync(FULLMASK, s, o);
    __shared__ float sm[4];
    if ((t & 31) == 0) sm[t >> 5] = s;
    __syncthreads();
    if (t == 0) g_bv[row] = (sm[0] + sm[1]) + (sm[2] + sm[3]);
}

// ---- block reductions over 512 threads (16 warps) ---------------------------
__device__ __forceinline__ float blk_sum(float v, float* sm) {
    #pragma unroll
    for (int o = 16; o; o >>= 1) v += __shfl_xor_sync(FULLMASK, v, o);
    const int lane = threadIdx.x & 31, w = threadIdx.x >> 5;
    if (lane == 0) sm[w] = v;
    __syncthreads();
    if (threadIdx.x < 32) {
        v = (lane < 16) ? sm[lane] : 0.f;
        #pragma unroll
        for (int o = 8; o; o >>= 1) v += __shfl_xor_sync(FULLMASK, v, o);
        if (lane == 0) sm[0] = v;
    }
    __syncthreads();
    float r = sm[0];
    __syncthreads();
    return r;
}

__device__ __forceinline__ float blk_max(float v, float* sm) {
    #pragma unroll
    for (int o = 16; o; o >>= 1) v = fmaxf(v, __shfl_xor_sync(FULLMASK, v, o));
    const int lane = threadIdx.x & 31, w = threadIdx.x >> 5;
    if (lane == 0) sm[w] = v;
    __syncthreads();
    if (threadIdx.x < 32) {
        v = (lane < 16) ? sm[lane] : -3.4e38f;
        #pragma unroll
        for (int o = 8; o; o >>= 1) v = fmaxf(v, __shfl_xor_sync(FULLMASK, v, o));
        if (lane == 0) sm[0] = v;
    }
    __syncthreads();
    float r = sm[0];
    __syncthreads();
    return r;
}

// ---- K2b: scalar stats, x_tmp, x_sparse, scale, norm coeff ------------------
__global__ void k_stats() {
    __shared__ float sm[32];
    const int t = threadIdx.x;          // exactly 512 threads
    const float a = g_xavr[t];
    const float b = g_bv[t];

    const float inh = blk_sum(b, sm) * (1.0f / (float)C);
    float xt = a + b - 2.0f * inh;
    xt = xt > 0.f ? xt : 0.f;

    const float thr = blk_max(xt, sm) * 0.9f;
    const float xs = (xt < thr) ? 0.f : xt;

    g_xtmp[t]    = xt;
    g_xsparse[t] = xs;
    g_scale[t]   = xt / (a + 1e-12f);

    const float st2 = blk_sum(xt * xt, sm);           // sum x_tmp^2
    const float ss2 = blk_sum(xs * xs, sm);           // sum x_sparse^2
    const float ts  = xt * xs;
    const float sd2 = blk_sum(ts * ts, sm);           // sum diag^2

    if (t == 0) {
        const float n2 = st2 * ss2 - sd2;             // ||outer zero-diag||_F^2
        const float n  = sqrtf(n2);
        float coeff = 0.05f;
        if (isfinite(n) && n > 0.f) coeff = 0.05f / n;
        g_coeff = coeff;
    }
}

// ---- K3: out = x * scale[c]  (2-D grid: y = channel) -------------------------
__global__ void k_apply(const float* __restrict__ x, float* __restrict__ out, int hw4) {
    const int c = blockIdx.y;
    const float sc = g_scale[c];
    const size_t base = (size_t)c * hw4;
    const int i = blockIdx.x * blockDim.x + threadIdx.x;
    if (i < hw4) {
        float4 v = __ldg(reinterpret_cast<const float4*>(x) + base + i);
        v.x *= sc; v.y *= sc; v.z *= sc; v.w *= sc;
        reinterpret_cast<float4*>(out)[base + i] = v;
    }
}

// ---- K4: new_boost_weight ----------------------------------------------------
__global__ void k_bw(const float* __restrict__ bw, float* __restrict__ out) {
    const int j = blockIdx.x * blockDim.x + threadIdx.x;   // over C*C
    const int i = j >> 9, col = j & (C - 1);
    const float wt = (i == col) ? 0.f : g_xtmp[i] * g_xsparse[col];
    out[j] = bw[j] * 0.5f + g_coeff * wt;
}

// ---- launch -------------------------------------------------------------------
extern "C" void kernel_launch(void* const* d_in, const int* in_sizes, int n_in,
                              void* d_out, int out_size) {
    // identify inputs robustly by size (x is the big one)
    int xi = 0, bi = 1;
    if (n_in >= 2 && in_sizes[0] < in_sizes[1]) { xi = 1; bi = 0; }
    const float* x  = (const float*)d_in[xi];
    const float* bw = (const float*)d_in[bi];
    float* out = (float*)d_out;

    const int n0 = in_sizes[xi];        // 512 * 448 * 448
    const int hw = n0 / C;              // 200704
    const int hw4 = hw >> 2;            // 50176 (divisible by 256)

    k_channel_mean<<<C, 1024>>>(x, hw);
    k_matvec<<<C, 128>>>(bw);
    k_stats<<<1, C>>>();

    dim3 grid((hw4 + 255) / 256, C);
    k_apply<<<grid, 256>>>(x, out, hw4);

    if (out_size >= n0 + C * C) {
        k_bw<<<(C * C) / 256, 256>>>(bw, out + n0);
    }
}

// round 2
// speedup vs baseline: 1.0106x; 1.0106x over previous
#include <cuda_runtime.h>

#define C 512
#define NSEG 4
#define FULLMASK 0xffffffffu

// ---- scratch (no allocs allowed) -------------------------------------------
__device__ float g_part[C][NSEG];   // partial channel sums
__device__ float g_bv[C];
__device__ float g_xtmp[C];
__device__ float g_xsparse[C];
__device__ float g_scale[C];
__device__ float g_coeff;           // 0.05 / norm (or 0.05 if norm invalid)

// ---- K1: per-channel partial sums (NSEG segments per channel) ----------------
__global__ void k_channel_mean(const float* __restrict__ x, int n4) {
    const int c   = blockIdx.y;
    const int seg = blockIdx.x;
    const float4* xp = reinterpret_cast<const float4*>(x) + (size_t)c * n4;
    const int lo = (n4 * seg) / NSEG;
    const int hi = (n4 * (seg + 1)) / NSEG;
    float s = 0.f;
    for (int i = lo + threadIdx.x; i < hi; i += blockDim.x) {
        float4 v = __ldcs(xp + i);
        s += (v.x + v.y) + (v.z + v.w);
    }
    __shared__ float sm[8];
    #pragma unroll
    for (int o = 16; o; o >>= 1) s += __shfl_xor_sync(FULLMASK, s, o);
    const int lane = threadIdx.x & 31, w = threadIdx.x >> 5;
    if (lane == 0) sm[w] = s;
    __syncthreads();
    if (threadIdx.x == 0) {
        float t = 0.f;
        #pragma unroll
        for (int k = 0; k < 8; k++) t += sm[k];
        g_part[c][seg] = t;
    }
}

__device__ __forceinline__ float channel_avg(int ch, float inv_hw) {
    return (g_part[ch][0] + g_part[ch][1] + g_part[ch][2] + g_part[ch][3]) * inv_hw;
}

// ---- K2a: boost_vec = W @ x_avr (one row per block, 128 threads) ------------
__global__ void k_matvec(const float* __restrict__ W, float inv_hw) {
    __shared__ float av[C];
    const int t = threadIdx.x;  // 128 threads
    #pragma unroll
    for (int j = t; j < C; j += 128) av[j] = channel_avg(j, inv_hw);
    __syncthreads();
    const int row = blockIdx.x;
    float4 wv = __ldg(reinterpret_cast<const float4*>(W + (size_t)row * C) + t);
    float s = wv.x * av[4*t] + wv.y * av[4*t+1] + wv.z * av[4*t+2] + wv.w * av[4*t+3];
    #pragma unroll
    for (int o = 16; o; o >>= 1) s += __shfl_xor_sync(FULLMASK, s, o);
    __shared__ float sm[4];
    if ((t & 31) == 0) sm[t >> 5] = s;
    __syncthreads();
    if (t == 0) g_bv[row] = (sm[0] + sm[1]) + (sm[2] + sm[3]);
}

// ---- block reductions over 512 threads (16 warps) ---------------------------
__device__ __forceinline__ float blk_sum(float v, float* sm) {
    #pragma unroll
    for (int o = 16; o; o >>= 1) v += __shfl_xor_sync(FULLMASK, v, o);
    const int lane = threadIdx.x & 31, w = threadIdx.x >> 5;
    if (lane == 0) sm[w] = v;
    __syncthreads();
    if (threadIdx.x < 32) {
        v = (lane < 16) ? sm[lane] : 0.f;
        #pragma unroll
        for (int o = 8; o; o >>= 1) v += __shfl_xor_sync(FULLMASK, v, o);
        if (lane == 0) sm[0] = v;
    }
    __syncthreads();
    float r = sm[0];
    __syncthreads();
    return r;
}

__device__ __forceinline__ float blk_max(float v, float* sm) {
    #pragma unroll
    for (int o = 16; o; o >>= 1) v = fmaxf(v, __shfl_xor_sync(FULLMASK, v, o));
    const int lane = threadIdx.x & 31, w = threadIdx.x >> 5;
    if (lane == 0) sm[w] = v;
    __syncthreads();
    if (threadIdx.x < 32) {
        v = (lane < 16) ? sm[lane] : -3.4e38f;
        #pragma unroll
        for (int o = 8; o; o >>= 1) v = fmaxf(v, __shfl_xor_sync(FULLMASK, v, o));
        if (lane == 0) sm[0] = v;
    }
    __syncthreads();
    float r = sm[0];
    __syncthreads();
    return r;
}

// ---- K2b: scalar stats, x_tmp, x_sparse, scale, norm coeff ------------------
__global__ void k_stats(float inv_hw) {
    __shared__ float sm[32];
    const int t = threadIdx.x;          // exactly 512 threads
    const float a = channel_avg(t, inv_hw);
    const float b = g_bv[t];

    const float inh = blk_sum(b, sm) * (1.0f / (float)C);
    float xt = a + b - 2.0f * inh;
    xt = xt > 0.f ? xt : 0.f;

    const float thr = blk_max(xt, sm) * 0.9f;
    const float xs = (xt < thr) ? 0.f : xt;

    g_xtmp[t]    = xt;
    g_xsparse[t] = xs;
    g_scale[t]   = xt / (a + 1e-12f);

    const float st2 = blk_sum(xt * xt, sm);           // sum x_tmp^2
    const float ss2 = blk_sum(xs * xs, sm);           // sum x_sparse^2
    const float ts  = xt * xs;
    const float sd2 = blk_sum(ts * ts, sm);           // sum diag^2

    if (t == 0) {
        const float n2 = st2 * ss2 - sd2;             // ||outer zero-diag||_F^2
        const float n  = sqrtf(n2);
        float coeff = 0.05f;
        if (isfinite(n) && n > 0.f) coeff = 0.05f / n;
        g_coeff = coeff;
    }
}

// ---- K3: out = x * scale[c]  (4 front-batched float4 per thread) -------------
__global__ void k_apply(const float* __restrict__ x, float* __restrict__ out, int hw4) {
    const int c = blockIdx.y;
    const float sc = g_scale[c];
    const size_t base = (size_t)c * hw4;
    const float4* xp = reinterpret_cast<const float4*>(x) + base;
    float4*       op = reinterpret_cast<float4*>(out) + base;

    const int i0 = blockIdx.x * 1024 + threadIdx.x;
    const int i1 = i0 + 256, i2 = i0 + 512, i3 = i0 + 768;
    const bool b0 = i0 < hw4, b1 = i1 < hw4, b2 = i2 < hw4, b3 = i3 < hw4;

    float4 v0, v1, v2, v3;
    if (b0) v0 = __ldcs(xp + i0);
    if (b1) v1 = __ldcs(xp + i1);
    if (b2) v2 = __ldcs(xp + i2);
    if (b3) v3 = __ldcs(xp + i3);

    if (b0) { v0.x *= sc; v0.y *= sc; v0.z *= sc; v0.w *= sc; __stcs(op + i0, v0); }
    if (b1) { v1.x *= sc; v1.y *= sc; v1.z *= sc; v1.w *= sc; __stcs(op + i1, v1); }
    if (b2) { v2.x *= sc; v2.y *= sc; v2.z *= sc; v2.w *= sc; __stcs(op + i2, v2); }
    if (b3) { v3.x *= sc; v3.y *= sc; v3.z *= sc; v3.w *= sc; __stcs(op + i3, v3); }
}

// ---- K4: new_boost_weight ----------------------------------------------------
__global__ void k_bw(const float* __restrict__ bw, float* __restrict__ out) {
    const int j = blockIdx.x * blockDim.x + threadIdx.x;   // over C*C
    const int i = j >> 9, col = j & (C - 1);
    const float wt = (i == col) ? 0.f : g_xtmp[i] * g_xsparse[col];
    out[j] = bw[j] * 0.5f + g_coeff * wt;
}

// ---- launch -------------------------------------------------------------------
extern "C" void kernel_launch(void* const* d_in, const int* in_sizes, int n_in,
                              void* d_out, int out_size) {
    // identify inputs robustly by size (x is the big one)
    int xi = 0, bi = 1;
    if (n_in >= 2 && in_sizes[0] < in_sizes[1]) { xi = 1; bi = 0; }
    const float* x  = (const float*)d_in[xi];
    const float* bw = (const float*)d_in[bi];
    float* out = (float*)d_out;

    const int n0 = in_sizes[xi];        // 512 * 448 * 448
    const int hw = n0 / C;              // 200704
    const int hw4 = hw >> 2;            // 50176
    const float inv_hw = 1.0f / (float)hw;

    dim3 gmean(NSEG, C);
    k_channel_mean<<<gmean, 256>>>(x, hw4);
    k_matvec<<<C, 128>>>(bw, inv_hw);
    k_stats<<<1, C>>>(inv_hw);

    dim3 gapply((hw4 + 1023) / 1024, C);
    k_apply<<<gapply, 256>>>(x, out, hw4);

    if (out_size >= n0 + C * C) {
        k_bw<<<(C * C) / 256, 256>>>(bw, out + n0);
    }
}